// round 11
// baseline (speedup 1.0000x reference)
#include <cuda_runtime.h>
#include <cstdint>

#define S_  512
#define B_  64
#define C_  1024
#define V_  10
#define TS_ 128
#define K_  64            // chunk length
#define NQ_ (S_ / K_)     // 8 chunks
#define G_  8             // group size within chunk
#define LN_EPS_ 1e-5f

typedef unsigned long long ull;

// Scratch (allocation-free rule: __device__ globals)
__device__ float  g_P[(size_t)S_ * B_ * TS_];      // pos at step t [t][b][l] (16 MB)
__device__ float4 g_hd[(size_t)S_ * B_];           // (d0,d1,d2,w) per (t,b)
__device__ float  g_Gd[(size_t)B_ * NQ_ * 8 * 64]; // diag 8x8 Gram blocks (1 MB)
__device__ float  g_tape[(size_t)TS_ * B_ * C_];   // final tape [l][b][c] (32 MB)

// ---- packed fp32x2 helpers ----
__device__ __forceinline__ ull fma2(ull a, ull b, ull c) {
    ull d;
    asm("fma.rn.f32x2 %0, %1, %2, %3;" : "=l"(d) : "l"(a), "l"(b), "l"(c));
    return d;
}
__device__ __forceinline__ ull add2(ull a, ull b) {
    ull d;
    asm("add.rn.f32x2 %0, %1, %2;" : "=l"(d) : "l"(a), "l"(b));
    return d;
}
__device__ __forceinline__ ull pk2(float lo, float hi) {
    ull r;
    asm("mov.b64 %0, {%1, %2};" : "=l"(r) : "f"(lo), "f"(hi));
    return r;
}
__device__ __forceinline__ float2 upk2(ull x) {
    float2 r;
    asm("mov.b64 {%0, %1}, %2;" : "=f"(r.x), "=f"(r.y) : "l"(x));
    return r;
}
__device__ __forceinline__ void cpa16(void* s, const void* g) {
    unsigned sa = (unsigned)__cvta_generic_to_shared(s);
    asm volatile("cp.async.ca.shared.global [%0], [%1], 16;" :: "r"(sa), "l"(g));
}
__device__ __forceinline__ void cpa_commit_waitall() {
    asm volatile("cp.async.commit_group;");
    asm volatile("cp.async.wait_group 0;" ::: "memory");
}

// ---------------------------------------------------------------------------
// Phase A: heads. dir = softmax(v@Wd^T+bd), w = sigmoid(v@Wr[1]+br[1]).
// 32 rows per block (warp loops 4 rows) to amortize the weight staging.
// ---------------------------------------------------------------------------
__global__ void __launch_bounds__(256) heads_kernel(
    const float* __restrict__ vals,
    const float* __restrict__ Wd, const float* __restrict__ bd,
    const float* __restrict__ Wr, const float* __restrict__ br)
{
    __shared__ float sW[4 * C_];
    int tid = threadIdx.x;
    for (int i = tid; i < 3 * C_; i += 256) sW[i] = Wd[i];
    for (int i = tid; i < C_;     i += 256) sW[3 * C_ + i] = Wr[C_ + i];
    __syncthreads();

    int wp = tid >> 5, lane = tid & 31;
    const float4* w4 = reinterpret_cast<const float4*>(sW);

    #pragma unroll 1
    for (int r = 0; r < 4; r++) {
        int row = blockIdx.x * 32 + wp * 4 + r;        // row = t*B + b
        const float4* v4 = reinterpret_cast<const float4*>(vals + (size_t)row * C_);

        float a0 = 0.f, a1 = 0.f, a2 = 0.f, a3 = 0.f;
        for (int i = lane; i < C_ / 4; i += 32) {
            float4 v = v4[i];
            float4 w;
            w = w4[i];       a0 += v.x*w.x + v.y*w.y + v.z*w.z + v.w*w.w;
            w = w4[256 + i]; a1 += v.x*w.x + v.y*w.y + v.z*w.z + v.w*w.w;
            w = w4[512 + i]; a2 += v.x*w.x + v.y*w.y + v.z*w.z + v.w*w.w;
            w = w4[768 + i]; a3 += v.x*w.x + v.y*w.y + v.z*w.z + v.w*w.w;
        }
        #pragma unroll
        for (int o = 16; o; o >>= 1) {
            a0 += __shfl_xor_sync(0xffffffffu, a0, o);
            a1 += __shfl_xor_sync(0xffffffffu, a1, o);
            a2 += __shfl_xor_sync(0xffffffffu, a2, o);
            a3 += __shfl_xor_sync(0xffffffffu, a3, o);
        }
        if (lane == 0) {
            float z0 = a0 + bd[0], z1 = a1 + bd[1], z2 = a2 + bd[2];
            float m  = fmaxf(z0, fmaxf(z1, z2));
            float e0 = expf(z0 - m), e1 = expf(z1 - m), e2 = expf(z2 - m);
            float inv = 1.f / (e0 + e1 + e2);
            float wg  = 1.f / (1.f + expf(-(a3 + br[1])));
            g_hd[row] = make_float4(e0 * inv, e1 * inv, e2 * inv, wg);
        }
    }
}

// ---------------------------------------------------------------------------
// Phase B: pos evolution. One warp per batch, 4 slots/lane, shuffle neighbors.
// ---------------------------------------------------------------------------
__global__ void __launch_bounds__(256) pos_kernel()
{
    int wp = threadIdx.x >> 5, lane = threadIdx.x & 31;
    int b = blockIdx.x * 8 + wp;
    float p0 = (lane == 0) ? 1.f : 0.f, p1 = 0.f, p2 = 0.f, p3 = 0.f;

    float4 D0 = g_hd[0 * B_ + b];
    float4 D1 = g_hd[1 * B_ + b];
    float4 D2 = g_hd[2 * B_ + b];
    float4 D3 = g_hd[3 * B_ + b];

    for (int t = 0; t < S_; t += 4) {
        #pragma unroll
        for (int k = 0; k < 4; k++) {
            int tt = t + k;
            float4* dst = reinterpret_cast<float4*>(g_P + ((size_t)tt * B_ + b) * TS_);
            dst[lane] = make_float4(p0, p1, p2, p3);
            float4 Dk = (k == 0) ? D0 : (k == 1) ? D1 : (k == 2) ? D2 : D3;
            float4 Dn = g_hd[(size_t)min(tt + 4, S_ - 1) * B_ + b];
            if (k == 0) D0 = Dn; else if (k == 1) D1 = Dn; else if (k == 2) D2 = Dn; else D3 = Dn;
            float d0 = Dk.x, d1 = Dk.y, d2 = Dk.z;
            float lw = __shfl_sync(0xffffffffu, p3, (lane + 31) & 31);
            float rw = __shfl_sync(0xffffffffu, p0, (lane + 1)  & 31);
            float n0 = p1 * d0 + p0 * d1 + lw * d2;
            float n1 = p2 * d0 + p1 * d1 + p0 * d2;
            float n2 = p3 * d0 + p2 * d1 + p1 * d2;
            float n3 = rw * d0 + p3 * d1 + p2 * d2;
            p0 = n0; p1 = n1; p2 = n2; p3 = n3;
        }
    }
}

// ---------------------------------------------------------------------------
// Phase B2: diagonal 8x8 Gram blocks: Gd[b][q][g][jj][j] =
//   p_{T0+8g+jj} . p_{T0+8g+j}
// ---------------------------------------------------------------------------
__global__ void __launch_bounds__(256) gramd_kernel()
{
    __shared__ float sPg[K_][132];
    int tid = threadIdx.x;
    int b = blockIdx.x >> 3, q = blockIdx.x & 7;
    int T0 = q * K_;

    for (int idx = tid; idx < K_ * TS_; idx += 256) {
        int t = idx >> 7, l = idx & 127;
        sPg[t][l] = g_P[((size_t)(T0 + t) * B_ + b) * TS_ + l];
    }
    __syncthreads();

    int w = tid >> 5, lane = tid & 31;   // warp w handles group w
    float* out = g_Gd + (size_t)blockIdx.x * 512 + w * 64;
    #pragma unroll
    for (int e = lane; e < 64; e += 32) {
        int jj = e >> 3, j = e & 7;
        const float* ra = sPg[w * 8 + jj];
        const float* rb = sPg[w * 8 + j];
        float d0 = 0.f, d1 = 0.f;
        #pragma unroll 8
        for (int k = 0; k < 32; k++) {
            float4 x = *reinterpret_cast<const float4*>(ra + 4 * k);
            float4 y = *reinterpret_cast<const float4*>(rb + 4 * k);
            d0 += x.x * y.x + x.y * y.y;
            d1 += x.z * y.z + x.w * y.w;
        }
        out[e] = d0 + d1;
    }
}

// ---------------------------------------------------------------------------
// Phase C: chunked tape scan — same phase structure as the verified 483us
// kernel, but half-width thread tiles (16 slots x 2 channels = 32 tape regs)
// with 512 threads/block -> 64-reg cap -> 2 CTAs x 16 warps = 32 warps/SM
// (2x the latency hiding). Block = (b, 128-channel group).
// Threads as 8(ty) x 64(tx). All warps share one ty (LDS broadcast kept).
// ---------------------------------------------------------------------------
__global__ void __launch_bounds__(512, 2) scan_kernel(const float* __restrict__ vals)
{
    extern __shared__ float sm[];
    float* sP    = sm;                   // [64][128]       8192 floats
    float* sv    = sP + K_ * TS_;        // [64][128]       8192 (v -> r -> a)
    float* spart = sv + K_ * TS_;        // [ty8][tl8][128] 8192
    float* sGd   = spart + 8 * G_ * TS_; // [g8][64]        512
    float* sw    = sGd + 8 * 64;         // [64]

    int tid = threadIdx.x;               // 0..511
    int ty  = tid >> 6;                  // 0..7 slot group
    int tx  = tid & 63;                  // 0..63 channel pair
    int b   = blockIdx.x >> 3;
    int cg  = blockIdx.x & 7;
    int c0  = cg << 7;

    const ull NEG1 = pk2(-1.f, -1.f);

    // tape tile regs: tp[sp][c]: slot pair (ty*16+2sp, +1), channel tx*2+c
    ull tp[8][2];
    #pragma unroll
    for (int sp = 0; sp < 8; sp++) { tp[sp][0] = 0ull; tp[sp][1] = 0ull; }

    for (int q = 0; q < NQ_; q++) {
        int T0 = q * K_;
        __syncthreads();   // protect sP/sv from previous iteration's readers
        // ---- stage P, v, Gd, w ----
        #pragma unroll
        for (int i = 0; i < 4; i++) {
            int idx = tid + 512 * i;
            int t = idx >> 5, seg = idx & 31;
            cpa16(sP + t * TS_ + seg * 4,
                  g_P + ((size_t)(T0 + t) * B_ + b) * TS_ + seg * 4);
        }
        #pragma unroll
        for (int i = 0; i < 4; i++) {
            int idx = tid + 512 * i;
            int t = idx >> 5, seg = idx & 31;
            cpa16(sv + t * TS_ + seg * 4,
                  vals + ((size_t)(T0 + t) * B_ + b) * C_ + c0 + seg * 4);
        }
        if (tid < 128)
            cpa16(sGd + tid * 4, g_Gd + (size_t)(b * NQ_ + q) * 512 + tid * 4);
        if (tid < K_)
            sw[tid] = g_hd[(size_t)(T0 + tid) * B_ + b].w;
        cpa_commit_waitall();
        __syncthreads();

        for (int g = 0; g < G_; g++) {
            int t0 = g * 8;

            // ---- phase1: partial ubase for the 8 t's of this group ----
            #pragma unroll 1
            for (int tl = 0; tl < 8; tl++) {
                const ull* pr = reinterpret_cast<const ull*>(
                    sP + (t0 + tl) * TS_) + ty * 8;
                ull a0 = 0ull, a1 = 0ull;
                #pragma unroll
                for (int sp = 0; sp < 8; sp++) {
                    ull p = pr[sp];
                    a0 = fma2(p, tp[sp][0], a0);
                    a1 = fma2(p, tp[sp][1], a1);
                }
                float2 f0 = upk2(a0), f1 = upk2(a1);
                *reinterpret_cast<float2*>(spart + ((ty * 8 + tl) * TS_) + tx * 2) =
                    make_float2(f0.x + f0.y, f1.x + f1.y);
            }
            __syncthreads();

            // ---- reduce partials into sv: r = v - ubase (1 ull cell/thread) ----
            {
                int tl = tid >> 6, cp = tid & 63;
                ull s = *reinterpret_cast<const ull*>(spart + tl * TS_ + cp * 2);
                #pragma unroll
                for (int yy = 1; yy < 8; yy++)
                    s = add2(s, *reinterpret_cast<const ull*>(
                                    spart + (yy * 8 + tl) * TS_ + cp * 2));
                ull* pv = reinterpret_cast<ull*>(sv + (t0 + tl) * TS_ + cp * 2);
                *pv = fma2(s, NEG1, *pv);
            }
            __syncthreads();

            // ---- solve: eager 8x8 triangular, one thread per channel ----
            if (tid < 128) {
                int c = tid;
                const float* Gg = sGd + g * 64;
                float at[8];
                #pragma unroll
                for (int j = 0; j < 8; j++) {
                    float u = 0.f;
                    #pragma unroll
                    for (int jj = 0; jj < 8; jj++)
                        if (jj < j) u += at[jj] * Gg[jj * 8 + j];
                    float a = sw[t0 + j] * (sv[(t0 + j) * TS_ + c] - u);
                    at[j] = a;
                    sv[(t0 + j) * TS_ + c] = a;
                }
            }
            __syncthreads();

            // ---- phase3: tape += p_t (x) a_t for the group ----
            #pragma unroll 1
            for (int tl = 0; tl < 8; tl++) {
                const ull* pr = reinterpret_cast<const ull*>(
                    sP + (t0 + tl) * TS_) + ty * 8;
                float2 av = *reinterpret_cast<const float2*>(sv + (t0 + tl) * TS_ + tx * 2);
                ull b0 = pk2(av.x, av.x), b1 = pk2(av.y, av.y);
                #pragma unroll
                for (int sp = 0; sp < 8; sp++) {
                    ull p = pr[sp];
                    tp[sp][0] = fma2(p, b0, tp[sp][0]);
                    tp[sp][1] = fma2(p, b1, tp[sp][1]);
                }
            }
        }
    }

    // ---- write final tape: coalesced STG.64 ----
    #pragma unroll
    for (int sp = 0; sp < 8; sp++) {
        float2 r0 = upk2(tp[sp][0]), r1 = upk2(tp[sp][1]);
        int l0 = ty * 16 + 2 * sp;
        float2* d0 = reinterpret_cast<float2*>(
            g_tape + ((size_t)l0 * B_ + b) * C_ + c0 + tx * 2);
        float2* d1 = reinterpret_cast<float2*>(
            g_tape + ((size_t)(l0 + 1) * B_ + b) * C_ + c0 + tx * 2);
        *d0 = make_float2(r0.x, r1.x);
        *d1 = make_float2(r0.y, r1.y);
    }
}

// ---------------------------------------------------------------------------
// Phase D: LayerNorm + out = h @ Wo^T + bo. Warp-per-row. grid = TS*B/8.
// ---------------------------------------------------------------------------
__global__ void __launch_bounds__(256) decode_kernel(
    const float* __restrict__ ln_g, const float* __restrict__ ln_b,
    const float* __restrict__ Wo,   const float* __restrict__ bo,
    float* __restrict__ out)
{
    __shared__ float sWo[V_ * C_];   // 40 KB
    int tid = threadIdx.x, lane = tid & 31, wp = tid >> 5;
    for (int i = tid; i < V_ * C_; i += 256) sWo[i] = Wo[i];
    __syncthreads();

    int row = blockIdx.x * 8 + wp;      // row = l*B + b
    const float4* src = reinterpret_cast<const float4*>(g_tape + (size_t)row * C_);
    float4 x[8];
    #pragma unroll
    for (int k = 0; k < 8; k++) x[k] = src[lane + 32 * k];

    float s = 0.f, qq = 0.f;
    #pragma unroll
    for (int k = 0; k < 8; k++) {
        s  += (x[k].x + x[k].y) + (x[k].z + x[k].w);
        qq += (x[k].x*x[k].x + x[k].y*x[k].y) + (x[k].z*x[k].z + x[k].w*x[k].w);
    }
    #pragma unroll
    for (int o = 16; o; o >>= 1) {
        s  += __shfl_xor_sync(0xffffffffu, s, o);
        qq += __shfl_xor_sync(0xffffffffu, qq, o);
    }
    float mu = s * (1.f / C_);
    float rstd = rsqrtf(qq * (1.f / C_) - mu * mu + LN_EPS_);

    const float4* g4 = reinterpret_cast<const float4*>(ln_g);
    const float4* e4 = reinterpret_cast<const float4*>(ln_b);
    #pragma unroll
    for (int k = 0; k < 8; k++) {
        float4 gg = g4[lane + 32 * k];
        float4 ee = e4[lane + 32 * k];
        x[k].x = (x[k].x - mu) * rstd * gg.x + ee.x;
        x[k].y = (x[k].y - mu) * rstd * gg.y + ee.y;
        x[k].z = (x[k].z - mu) * rstd * gg.z + ee.z;
        x[k].w = (x[k].w - mu) * rstd * gg.w + ee.w;
    }

    #pragma unroll
    for (int v = 0; v < V_; v++) {
        const float4* wv = reinterpret_cast<const float4*>(sWo + v * C_);
        float pp = 0.f;
        #pragma unroll
        for (int k = 0; k < 8; k++) {
            float4 w = wv[lane + 32 * k];
            pp += (x[k].x*w.x + x[k].y*w.y) + (x[k].z*w.z + x[k].w*w.w);
        }
        #pragma unroll
        for (int o = 16; o; o >>= 1) pp += __shfl_xor_sync(0xffffffffu, pp, o);
        if (lane == 0) out[(size_t)row * V_ + v] = pp + bo[v];
    }
}

// ---------------------------------------------------------------------------
extern "C" void kernel_launch(void* const* d_in, const int* in_sizes, int n_in,
                              void* d_out, int out_size)
{
    const float* vals = (const float*)d_in[0];
    const float* Wd   = (const float*)d_in[1];
    const float* bd   = (const float*)d_in[2];
    const float* Wr   = (const float*)d_in[3];
    const float* br   = (const float*)d_in[4];
    const float* lng  = (const float*)d_in[5];
    const float* lnb  = (const float*)d_in[6];
    const float* Wo   = (const float*)d_in[7];
    const float* bo   = (const float*)d_in[8];
    float* out = (float*)d_out;

    const int SMEM_SCAN = (K_ * TS_ + K_ * TS_ + 8 * G_ * TS_ + 8 * 64 + K_) * 4;
    cudaFuncSetAttribute(scan_kernel,
                         cudaFuncAttributeMaxDynamicSharedMemorySize, SMEM_SCAN);

    heads_kernel<<<(S_ * B_) / 32, 256>>>(vals, Wd, bd, Wr, br);
    pos_kernel<<<B_ / 8, 256>>>();
    gramd_kernel<<<B_ * NQ_, 256>>>();
    scan_kernel<<<B_ * (C_ / TS_), 512, SMEM_SCAN>>>(vals);
    decode_kernel<<<(TS_ * B_) / 8, 256>>>(lng, lnb, Wo, bo, out);
}

// round 12
// speedup vs baseline: 1.1052x; 1.1052x over previous
#include <cuda_runtime.h>
#include <cstdint>

#define S_  512
#define B_  64
#define C_  1024
#define V_  10
#define TS_ 128
#define K_  64            // chunk length
#define NQ_ (S_ / K_)     // 8 chunks
#define G_  8             // group size within chunk
#define LN_EPS_ 1e-5f

typedef unsigned long long ull;

// Scratch (allocation-free rule: __device__ globals)
__device__ float  g_P[(size_t)S_ * B_ * TS_];      // pos at step t [t][b][l] (16 MB)
__device__ float4 g_hd[(size_t)S_ * B_];           // (d0,d1,d2,w) per (t,b)
__device__ float  g_Gd[(size_t)B_ * NQ_ * 8 * 64]; // diag 8x8 Gram blocks (1 MB)
__device__ float  g_tape[(size_t)TS_ * B_ * C_];   // final tape [l][b][c] (32 MB)

// ---- packed fp32x2 helpers ----
__device__ __forceinline__ ull fma2(ull a, ull b, ull c) {
    ull d;
    asm("fma.rn.f32x2 %0, %1, %2, %3;" : "=l"(d) : "l"(a), "l"(b), "l"(c));
    return d;
}
__device__ __forceinline__ ull add2(ull a, ull b) {
    ull d;
    asm("add.rn.f32x2 %0, %1, %2;" : "=l"(d) : "l"(a), "l"(b));
    return d;
}
__device__ __forceinline__ ull pk2(float lo, float hi) {
    ull r;
    asm("mov.b64 %0, {%1, %2};" : "=l"(r) : "f"(lo), "f"(hi));
    return r;
}
__device__ __forceinline__ float2 upk2(ull x) {
    float2 r;
    asm("mov.b64 {%0, %1}, %2;" : "=f"(r.x), "=f"(r.y) : "l"(x));
    return r;
}
__device__ __forceinline__ void cpa16(void* s, const void* g) {
    unsigned sa = (unsigned)__cvta_generic_to_shared(s);
    asm volatile("cp.async.ca.shared.global [%0], [%1], 16;" :: "r"(sa), "l"(g));
}
__device__ __forceinline__ void cpa_commit_waitall() {
    asm volatile("cp.async.commit_group;");
    asm volatile("cp.async.wait_group 0;" ::: "memory");
}

// ---------------------------------------------------------------------------
// Phase A: heads. dir = softmax(v@Wd^T+bd), w = sigmoid(v@Wr[1]+br[1]).
// 32 rows per block (warp loops 4 rows) to amortize the weight staging.
// ---------------------------------------------------------------------------
__global__ void __launch_bounds__(256) heads_kernel(
    const float* __restrict__ vals,
    const float* __restrict__ Wd, const float* __restrict__ bd,
    const float* __restrict__ Wr, const float* __restrict__ br)
{
    __shared__ float sW[4 * C_];
    int tid = threadIdx.x;
    for (int i = tid; i < 3 * C_; i += 256) sW[i] = Wd[i];
    for (int i = tid; i < C_;     i += 256) sW[3 * C_ + i] = Wr[C_ + i];
    __syncthreads();

    int wp = tid >> 5, lane = tid & 31;
    const float4* w4 = reinterpret_cast<const float4*>(sW);

    #pragma unroll 1
    for (int r = 0; r < 4; r++) {
        int row = blockIdx.x * 32 + wp * 4 + r;        // row = t*B + b
        const float4* v4 = reinterpret_cast<const float4*>(vals + (size_t)row * C_);

        float a0 = 0.f, a1 = 0.f, a2 = 0.f, a3 = 0.f;
        for (int i = lane; i < C_ / 4; i += 32) {
            float4 v = v4[i];
            float4 w;
            w = w4[i];       a0 += v.x*w.x + v.y*w.y + v.z*w.z + v.w*w.w;
            w = w4[256 + i]; a1 += v.x*w.x + v.y*w.y + v.z*w.z + v.w*w.w;
            w = w4[512 + i]; a2 += v.x*w.x + v.y*w.y + v.z*w.z + v.w*w.w;
            w = w4[768 + i]; a3 += v.x*w.x + v.y*w.y + v.z*w.z + v.w*w.w;
        }
        #pragma unroll
        for (int o = 16; o; o >>= 1) {
            a0 += __shfl_xor_sync(0xffffffffu, a0, o);
            a1 += __shfl_xor_sync(0xffffffffu, a1, o);
            a2 += __shfl_xor_sync(0xffffffffu, a2, o);
            a3 += __shfl_xor_sync(0xffffffffu, a3, o);
        }
        if (lane == 0) {
            float z0 = a0 + bd[0], z1 = a1 + bd[1], z2 = a2 + bd[2];
            float m  = fmaxf(z0, fmaxf(z1, z2));
            float e0 = expf(z0 - m), e1 = expf(z1 - m), e2 = expf(z2 - m);
            float inv = 1.f / (e0 + e1 + e2);
            float wg  = 1.f / (1.f + expf(-(a3 + br[1])));
            g_hd[row] = make_float4(e0 * inv, e1 * inv, e2 * inv, wg);
        }
    }
}

// ---------------------------------------------------------------------------
// Phase B: pos evolution. One warp per batch, 4 slots/lane, shuffle neighbors.
// ---------------------------------------------------------------------------
__global__ void __launch_bounds__(256) pos_kernel()
{
    int wp = threadIdx.x >> 5, lane = threadIdx.x & 31;
    int b = blockIdx.x * 8 + wp;
    float p0 = (lane == 0) ? 1.f : 0.f, p1 = 0.f, p2 = 0.f, p3 = 0.f;

    float4 D0 = g_hd[0 * B_ + b];
    float4 D1 = g_hd[1 * B_ + b];
    float4 D2 = g_hd[2 * B_ + b];
    float4 D3 = g_hd[3 * B_ + b];

    for (int t = 0; t < S_; t += 4) {
        #pragma unroll
        for (int k = 0; k < 4; k++) {
            int tt = t + k;
            float4* dst = reinterpret_cast<float4*>(g_P + ((size_t)tt * B_ + b) * TS_);
            dst[lane] = make_float4(p0, p1, p2, p3);
            float4 Dk = (k == 0) ? D0 : (k == 1) ? D1 : (k == 2) ? D2 : D3;
            float4 Dn = g_hd[(size_t)min(tt + 4, S_ - 1) * B_ + b];
            if (k == 0) D0 = Dn; else if (k == 1) D1 = Dn; else if (k == 2) D2 = Dn; else D3 = Dn;
            float d0 = Dk.x, d1 = Dk.y, d2 = Dk.z;
            float lw = __shfl_sync(0xffffffffu, p3, (lane + 31) & 31);
            float rw = __shfl_sync(0xffffffffu, p0, (lane + 1)  & 31);
            float n0 = p1 * d0 + p0 * d1 + lw * d2;
            float n1 = p2 * d0 + p1 * d1 + p0 * d2;
            float n2 = p3 * d0 + p2 * d1 + p1 * d2;
            float n3 = rw * d0 + p3 * d1 + p2 * d2;
            p0 = n0; p1 = n1; p2 = n2; p3 = n3;
        }
    }
}

// ---------------------------------------------------------------------------
// Phase B2: diagonal 8x8 Gram blocks: Gd[b][q][g][jj][j] =
//   p_{T0+8g+jj} . p_{T0+8g+j}
// ---------------------------------------------------------------------------
__global__ void __launch_bounds__(256) gramd_kernel()
{
    __shared__ float sPg[K_][132];
    int tid = threadIdx.x;
    int b = blockIdx.x >> 3, q = blockIdx.x & 7;
    int T0 = q * K_;

    for (int idx = tid; idx < K_ * TS_; idx += 256) {
        int t = idx >> 7, l = idx & 127;
        sPg[t][l] = g_P[((size_t)(T0 + t) * B_ + b) * TS_ + l];
    }
    __syncthreads();

    int w = tid >> 5, lane = tid & 31;   // warp w handles group w
    float* out = g_Gd + (size_t)blockIdx.x * 512 + w * 64;
    #pragma unroll
    for (int e = lane; e < 64; e += 32) {
        int jj = e >> 3, j = e & 7;
        const float* ra = sPg[w * 8 + jj];
        const float* rb = sPg[w * 8 + j];
        float d0 = 0.f, d1 = 0.f;
        #pragma unroll 8
        for (int k = 0; k < 32; k++) {
            float4 x = *reinterpret_cast<const float4*>(ra + 4 * k);
            float4 y = *reinterpret_cast<const float4*>(rb + 4 * k);
            d0 += x.x * y.x + x.y * y.y;
            d1 += x.z * y.z + x.w * y.w;
        }
        out[e] = d0 + d1;
    }
}

// ---------------------------------------------------------------------------
// Phase C: chunked tape scan, 2-D register tiling — the verified 483us
// structure, with ONE change: phase1/phase3 pos loads are LDS.128
// (ulonglong2) instead of LDS.64, consumed in the identical order.
// Block = (b, 128-channel group). 256 threads as 8(ty) x 32(tx):
// thread tile = 16 slots x 4 channels.
// ---------------------------------------------------------------------------
__global__ void __launch_bounds__(256, 2) scan_kernel(const float* __restrict__ vals)
{
    extern __shared__ float sm[];
    float* sP    = sm;                   // [64][128]       8192 floats
    float* sv    = sP + K_ * TS_;        // [64][128]       8192 (v -> r -> a)
    float* spart = sv + K_ * TS_;        // [ty8][tl8][128] 8192
    float* sGd   = spart + 8 * G_ * TS_; // [g8][64]        512
    float* sw    = sGd + 8 * 64;         // [64]

    int tid = threadIdx.x;
    int ty  = tid >> 5;                  // 0..7 slot group
    int tx  = tid & 31;                  // 0..31 channel group
    int b   = blockIdx.x >> 3;
    int cg  = blockIdx.x & 7;
    int c0  = cg << 7;

    const ull NEG1 = pk2(-1.f, -1.f);

    // tape tile regs: tp[sp][c]: slot pair (ty*16+2sp, +1), channel tx*4+c
    ull tp[8][4];
    #pragma unroll
    for (int sp = 0; sp < 8; sp++)
        #pragma unroll
        for (int c = 0; c < 4; c++) tp[sp][c] = 0ull;

    for (int q = 0; q < NQ_; q++) {
        int T0 = q * K_;
        __syncthreads();   // protect sP/sv from previous iteration's readers
        // ---- stage P, v, Gd, w ----
        #pragma unroll
        for (int i = 0; i < 8; i++) {
            int idx = tid + 256 * i;
            int t = idx >> 5, seg = idx & 31;
            cpa16(sP + t * TS_ + seg * 4,
                  g_P + ((size_t)(T0 + t) * B_ + b) * TS_ + seg * 4);
        }
        #pragma unroll
        for (int i = 0; i < 8; i++) {
            int idx = tid + 256 * i;
            int t = idx >> 5, seg = idx & 31;
            cpa16(sv + t * TS_ + seg * 4,
                  vals + ((size_t)(T0 + t) * B_ + b) * C_ + c0 + seg * 4);
        }
        if (tid < 128)
            cpa16(sGd + tid * 4, g_Gd + (size_t)(b * NQ_ + q) * 512 + tid * 4);
        if (tid < K_)
            sw[tid] = g_hd[(size_t)(T0 + tid) * B_ + b].w;
        cpa_commit_waitall();
        __syncthreads();

        for (int g = 0; g < G_; g++) {
            int t0 = g * 8;

            // ---- phase1: partial ubase for the 8 t's of this group ----
            #pragma unroll 1
            for (int tl = 0; tl < 8; tl++) {
                const ulonglong2* pr = reinterpret_cast<const ulonglong2*>(
                    sP + (t0 + tl) * TS_) + ty * 4;
                ull a0 = 0ull, a1 = 0ull, a2 = 0ull, a3 = 0ull;
                #pragma unroll
                for (int k = 0; k < 4; k++) {
                    ulonglong2 p = pr[k];
                    a0 = fma2(p.x, tp[2 * k][0], a0);
                    a1 = fma2(p.x, tp[2 * k][1], a1);
                    a2 = fma2(p.x, tp[2 * k][2], a2);
                    a3 = fma2(p.x, tp[2 * k][3], a3);
                    a0 = fma2(p.y, tp[2 * k + 1][0], a0);
                    a1 = fma2(p.y, tp[2 * k + 1][1], a1);
                    a2 = fma2(p.y, tp[2 * k + 1][2], a2);
                    a3 = fma2(p.y, tp[2 * k + 1][3], a3);
                }
                float2 f0 = upk2(a0), f1 = upk2(a1), f2 = upk2(a2), f3 = upk2(a3);
                float4 st = make_float4(f0.x + f0.y, f1.x + f1.y,
                                        f2.x + f2.y, f3.x + f3.y);
                *reinterpret_cast<float4*>(spart + ((ty * 8 + tl) * TS_) + tx * 4) = st;
            }
            __syncthreads();

            // ---- reduce partials into sv: r = v - ubase ----
            #pragma unroll
            for (int rr = 0; rr < 2; rr++) {
                int cc = tid + rr * 256;         // ull cell in [0, 512)
                int tl = cc >> 6, cp = cc & 63;
                ull s = *reinterpret_cast<const ull*>(spart + tl * TS_ + cp * 2);
                #pragma unroll
                for (int yy = 1; yy < 8; yy++)
                    s = add2(s, *reinterpret_cast<const ull*>(
                                    spart + (yy * 8 + tl) * TS_ + cp * 2));
                ull* pv = reinterpret_cast<ull*>(sv + (t0 + tl) * TS_ + cp * 2);
                *pv = fma2(s, NEG1, *pv);
            }
            __syncthreads();

            // ---- solve: eager 8x8 triangular, one thread per channel ----
            if (tid < 128) {
                int c = tid;
                const float* Gg = sGd + g * 64;
                float at[8];
                #pragma unroll
                for (int j = 0; j < 8; j++) {
                    float u = 0.f;
                    #pragma unroll
                    for (int jj = 0; jj < 8; jj++)
                        if (jj < j) u += at[jj] * Gg[jj * 8 + j];
                    float a = sw[t0 + j] * (sv[(t0 + j) * TS_ + c] - u);
                    at[j] = a;
                    sv[(t0 + j) * TS_ + c] = a;
                }
            }
            __syncthreads();

            // ---- phase3: tape += p_t (x) a_t for the group ----
            #pragma unroll 1
            for (int tl = 0; tl < 8; tl++) {
                const ulonglong2* pr = reinterpret_cast<const ulonglong2*>(
                    sP + (t0 + tl) * TS_) + ty * 4;
                float4 av = *reinterpret_cast<const float4*>(sv + (t0 + tl) * TS_ + tx * 4);
                ull b0 = pk2(av.x, av.x), b1 = pk2(av.y, av.y);
                ull b2 = pk2(av.z, av.z), b3 = pk2(av.w, av.w);
                #pragma unroll
                for (int k = 0; k < 4; k++) {
                    ulonglong2 p = pr[k];
                    tp[2 * k][0] = fma2(p.x, b0, tp[2 * k][0]);
                    tp[2 * k][1] = fma2(p.x, b1, tp[2 * k][1]);
                    tp[2 * k][2] = fma2(p.x, b2, tp[2 * k][2]);
                    tp[2 * k][3] = fma2(p.x, b3, tp[2 * k][3]);
                    tp[2 * k + 1][0] = fma2(p.y, b0, tp[2 * k + 1][0]);
                    tp[2 * k + 1][1] = fma2(p.y, b1, tp[2 * k + 1][1]);
                    tp[2 * k + 1][2] = fma2(p.y, b2, tp[2 * k + 1][2]);
                    tp[2 * k + 1][3] = fma2(p.y, b3, tp[2 * k + 1][3]);
                }
            }
        }
    }

    // ---- write final tape: coalesced STG.128 ----
    #pragma unroll
    for (int sp = 0; sp < 8; sp++) {
        float2 r0 = upk2(tp[sp][0]), r1 = upk2(tp[sp][1]);
        float2 r2 = upk2(tp[sp][2]), r3 = upk2(tp[sp][3]);
        int l0 = ty * 16 + 2 * sp;
        float4* d0 = reinterpret_cast<float4*>(
            g_tape + ((size_t)l0 * B_ + b) * C_ + c0 + tx * 4);
        float4* d1 = reinterpret_cast<float4*>(
            g_tape + ((size_t)(l0 + 1) * B_ + b) * C_ + c0 + tx * 4);
        *d0 = make_float4(r0.x, r1.x, r2.x, r3.x);
        *d1 = make_float4(r0.y, r1.y, r2.y, r3.y);
    }
}

// ---------------------------------------------------------------------------
// Phase D: LayerNorm + out = h @ Wo^T + bo. Warp-per-row. grid = TS*B/8.
// ---------------------------------------------------------------------------
__global__ void __launch_bounds__(256) decode_kernel(
    const float* __restrict__ ln_g, const float* __restrict__ ln_b,
    const float* __restrict__ Wo,   const float* __restrict__ bo,
    float* __restrict__ out)
{
    __shared__ float sWo[V_ * C_];   // 40 KB
    int tid = threadIdx.x, lane = tid & 31, wp = tid >> 5;
    for (int i = tid; i < V_ * C_; i += 256) sWo[i] = Wo[i];
    __syncthreads();

    int row = blockIdx.x * 8 + wp;      // row = l*B + b
    const float4* src = reinterpret_cast<const float4*>(g_tape + (size_t)row * C_);
    float4 x[8];
    #pragma unroll
    for (int k = 0; k < 8; k++) x[k] = src[lane + 32 * k];

    float s = 0.f, qq = 0.f;
    #pragma unroll
    for (int k = 0; k < 8; k++) {
        s  += (x[k].x + x[k].y) + (x[k].z + x[k].w);
        qq += (x[k].x*x[k].x + x[k].y*x[k].y) + (x[k].z*x[k].z + x[k].w*x[k].w);
    }
    #pragma unroll
    for (int o = 16; o; o >>= 1) {
        s  += __shfl_xor_sync(0xffffffffu, s, o);
        qq += __shfl_xor_sync(0xffffffffu, qq, o);
    }
    float mu = s * (1.f / C_);
    float rstd = rsqrtf(qq * (1.f / C_) - mu * mu + LN_EPS_);

    const float4* g4 = reinterpret_cast<const float4*>(ln_g);
    const float4* e4 = reinterpret_cast<const float4*>(ln_b);
    #pragma unroll
    for (int k = 0; k < 8; k++) {
        float4 gg = g4[lane + 32 * k];
        float4 ee = e4[lane + 32 * k];
        x[k].x = (x[k].x - mu) * rstd * gg.x + ee.x;
        x[k].y = (x[k].y - mu) * rstd * gg.y + ee.y;
        x[k].z = (x[k].z - mu) * rstd * gg.z + ee.z;
        x[k].w = (x[k].w - mu) * rstd * gg.w + ee.w;
    }

    #pragma unroll
    for (int v = 0; v < V_; v++) {
        const float4* wv = reinterpret_cast<const float4*>(sWo + v * C_);
        float pp = 0.f;
        #pragma unroll
        for (int k = 0; k < 8; k++) {
            float4 w = wv[lane + 32 * k];
            pp += (x[k].x*w.x + x[k].y*w.y) + (x[k].z*w.z + x[k].w*w.w);
        }
        #pragma unroll
        for (int o = 16; o; o >>= 1) pp += __shfl_xor_sync(0xffffffffu, pp, o);
        if (lane == 0) out[(size_t)row * V_ + v] = pp + bo[v];
    }
}

// ---------------------------------------------------------------------------
extern "C" void kernel_launch(void* const* d_in, const int* in_sizes, int n_in,
                              void* d_out, int out_size)
{
    const float* vals = (const float*)d_in[0];
    const float* Wd   = (const float*)d_in[1];
    const float* bd   = (const float*)d_in[2];
    const float* Wr   = (const float*)d_in[3];
    const float* br   = (const float*)d_in[4];
    const float* lng  = (const float*)d_in[5];
    const float* lnb  = (const float*)d_in[6];
    const float* Wo   = (const float*)d_in[7];
    const float* bo   = (const float*)d_in[8];
    float* out = (float*)d_out;

    const int SMEM_SCAN = (K_ * TS_ + K_ * TS_ + 8 * G_ * TS_ + 8 * 64 + K_) * 4;
    cudaFuncSetAttribute(scan_kernel,
                         cudaFuncAttributeMaxDynamicSharedMemorySize, SMEM_SCAN);

    heads_kernel<<<(S_ * B_) / 32, 256>>>(vals, Wd, bd, Wr, br);
    pos_kernel<<<B_ / 8, 256>>>();
    gramd_kernel<<<B_ * NQ_, 256>>>();
    scan_kernel<<<B_ * (C_ / TS_), 256, SMEM_SCAN>>>(vals);
    decode_kernel<<<(TS_ * B_) / 8, 256>>>(lng, lnb, Wo, bo, out);
}

// round 13
// speedup vs baseline: 1.1713x; 1.0598x over previous
#include <cuda_runtime.h>
#include <cstdint>

#define S_  512
#define B_  64
#define C_  1024
#define V_  10
#define TS_ 128
#define K_  64            // chunk length
#define NQ_ (S_ / K_)     // 8 chunks
#define G_  8             // group size within chunk
#define LN_EPS_ 1e-5f

typedef unsigned long long ull;

// Scratch (allocation-free rule: __device__ globals)
__device__ float  g_P[(size_t)S_ * B_ * TS_];      // pos at step t [t][b][l] (16 MB)
__device__ float4 g_hd[(size_t)S_ * B_];           // (d0,d1,d2,w) per (t,b)
__device__ float  g_Gd[(size_t)B_ * NQ_ * 8 * 64]; // diag 8x8 Gram blocks (1 MB)
__device__ float  g_tape[(size_t)TS_ * B_ * C_];   // final tape [l][b][c] (32 MB)

// ---- packed fp32x2 helpers ----
__device__ __forceinline__ ull fma2(ull a, ull b, ull c) {
    ull d;
    asm("fma.rn.f32x2 %0, %1, %2, %3;" : "=l"(d) : "l"(a), "l"(b), "l"(c));
    return d;
}
__device__ __forceinline__ ull add2(ull a, ull b) {
    ull d;
    asm("add.rn.f32x2 %0, %1, %2;" : "=l"(d) : "l"(a), "l"(b));
    return d;
}
__device__ __forceinline__ ull pk2(float lo, float hi) {
    ull r;
    asm("mov.b64 %0, {%1, %2};" : "=l"(r) : "f"(lo), "f"(hi));
    return r;
}
__device__ __forceinline__ float2 upk2(ull x) {
    float2 r;
    asm("mov.b64 {%0, %1}, %2;" : "=f"(r.x), "=f"(r.y) : "l"(x));
    return r;
}
__device__ __forceinline__ void cpa16(void* s, const void* g) {
    unsigned sa = (unsigned)__cvta_generic_to_shared(s);
    asm volatile("cp.async.ca.shared.global [%0], [%1], 16;" :: "r"(sa), "l"(g));
}
__device__ __forceinline__ void cpa_commit_waitall() {
    asm volatile("cp.async.commit_group;");
    asm volatile("cp.async.wait_group 0;" ::: "memory");
}

// ---------------------------------------------------------------------------
// Phase A: heads. dir = softmax(v@Wd^T+bd), w = sigmoid(v@Wr[1]+br[1]).
// 32 rows per block (warp loops 4 rows) to amortize the weight staging.
// ---------------------------------------------------------------------------
__global__ void __launch_bounds__(256) heads_kernel(
    const float* __restrict__ vals,
    const float* __restrict__ Wd, const float* __restrict__ bd,
    const float* __restrict__ Wr, const float* __restrict__ br)
{
    __shared__ float sW[4 * C_];
    int tid = threadIdx.x;
    for (int i = tid; i < 3 * C_; i += 256) sW[i] = Wd[i];
    for (int i = tid; i < C_;     i += 256) sW[3 * C_ + i] = Wr[C_ + i];
    __syncthreads();

    int wp = tid >> 5, lane = tid & 31;
    const float4* w4 = reinterpret_cast<const float4*>(sW);

    #pragma unroll 1
    for (int r = 0; r < 4; r++) {
        int row = blockIdx.x * 32 + wp * 4 + r;        // row = t*B + b
        const float4* v4 = reinterpret_cast<const float4*>(vals + (size_t)row * C_);

        float a0 = 0.f, a1 = 0.f, a2 = 0.f, a3 = 0.f;
        for (int i = lane; i < C_ / 4; i += 32) {
            float4 v = v4[i];
            float4 w;
            w = w4[i];       a0 += v.x*w.x + v.y*w.y + v.z*w.z + v.w*w.w;
            w = w4[256 + i]; a1 += v.x*w.x + v.y*w.y + v.z*w.z + v.w*w.w;
            w = w4[512 + i]; a2 += v.x*w.x + v.y*w.y + v.z*w.z + v.w*w.w;
            w = w4[768 + i]; a3 += v.x*w.x + v.y*w.y + v.z*w.z + v.w*w.w;
        }
        #pragma unroll
        for (int o = 16; o; o >>= 1) {
            a0 += __shfl_xor_sync(0xffffffffu, a0, o);
            a1 += __shfl_xor_sync(0xffffffffu, a1, o);
            a2 += __shfl_xor_sync(0xffffffffu, a2, o);
            a3 += __shfl_xor_sync(0xffffffffu, a3, o);
        }
        if (lane == 0) {
            float z0 = a0 + bd[0], z1 = a1 + bd[1], z2 = a2 + bd[2];
            float m  = fmaxf(z0, fmaxf(z1, z2));
            float e0 = expf(z0 - m), e1 = expf(z1 - m), e2 = expf(z2 - m);
            float inv = 1.f / (e0 + e1 + e2);
            float wg  = 1.f / (1.f + expf(-(a3 + br[1])));
            g_hd[row] = make_float4(e0 * inv, e1 * inv, e2 * inv, wg);
        }
    }
}

// ---------------------------------------------------------------------------
// Phase B: pos evolution. One warp per batch, 4 slots/lane, shuffle neighbors.
// Depth-8 prefetch ring on g_hd so the ~250-cyc L2 latency stays covered.
// ---------------------------------------------------------------------------
__global__ void __launch_bounds__(256) pos_kernel()
{
    int wp = threadIdx.x >> 5, lane = threadIdx.x & 31;
    int b = blockIdx.x * 8 + wp;
    float p0 = (lane == 0) ? 1.f : 0.f, p1 = 0.f, p2 = 0.f, p3 = 0.f;

    float4 D[8];
    #pragma unroll
    for (int k = 0; k < 8; k++) D[k] = g_hd[(size_t)k * B_ + b];

    for (int t = 0; t < S_; t += 8) {
        #pragma unroll
        for (int k = 0; k < 8; k++) {
            int tt = t + k;
            float4* dst = reinterpret_cast<float4*>(g_P + ((size_t)tt * B_ + b) * TS_);
            dst[lane] = make_float4(p0, p1, p2, p3);
            float4 Dk = D[k];
            D[k] = g_hd[(size_t)min(tt + 8, S_ - 1) * B_ + b];
            float d0 = Dk.x, d1 = Dk.y, d2 = Dk.z;
            float lw = __shfl_sync(0xffffffffu, p3, (lane + 31) & 31);
            float rw = __shfl_sync(0xffffffffu, p0, (lane + 1)  & 31);
            float n0 = p1 * d0 + p0 * d1 + lw * d2;
            float n1 = p2 * d0 + p1 * d1 + p0 * d2;
            float n2 = p3 * d0 + p2 * d1 + p1 * d2;
            float n3 = rw * d0 + p3 * d1 + p2 * d2;
            p0 = n0; p1 = n1; p2 = n2; p3 = n3;
        }
    }
}

// ---------------------------------------------------------------------------
// Phase B2: diagonal 8x8 Gram blocks: Gd[b][q][g][jj][j] =
//   p_{T0+8g+jj} . p_{T0+8g+j}
// ---------------------------------------------------------------------------
__global__ void __launch_bounds__(256) gramd_kernel()
{
    __shared__ float sPg[K_][132];
    int tid = threadIdx.x;
    int b = blockIdx.x >> 3, q = blockIdx.x & 7;
    int T0 = q * K_;

    for (int idx = tid; idx < K_ * TS_; idx += 256) {
        int t = idx >> 7, l = idx & 127;
        sPg[t][l] = g_P[((size_t)(T0 + t) * B_ + b) * TS_ + l];
    }
    __syncthreads();

    int w = tid >> 5, lane = tid & 31;   // warp w handles group w
    float* out = g_Gd + (size_t)blockIdx.x * 512 + w * 64;
    #pragma unroll
    for (int e = lane; e < 64; e += 32) {
        int jj = e >> 3, j = e & 7;
        const float* ra = sPg[w * 8 + jj];
        const float* rb = sPg[w * 8 + j];
        float d0 = 0.f, d1 = 0.f;
        #pragma unroll 8
        for (int k = 0; k < 32; k++) {
            float4 x = *reinterpret_cast<const float4*>(ra + 4 * k);
            float4 y = *reinterpret_cast<const float4*>(rb + 4 * k);
            d0 += x.x * y.x + x.y * y.y;
            d1 += x.z * y.z + x.w * y.w;
        }
        out[e] = d0 + d1;
    }
}

// ---------------------------------------------------------------------------
// Phase C: chunked tape scan, 2-D register tiling — verified 484us structure,
// UNCHANGED. Block = (b, 128-channel group). 256 threads as 8(ty) x 32(tx):
// thread tile = 16 slots x 4 channels.
// ---------------------------------------------------------------------------
__global__ void __launch_bounds__(256, 2) scan_kernel(const float* __restrict__ vals)
{
    extern __shared__ float sm[];
    float* sP    = sm;                   // [64][128]       8192 floats
    float* sv    = sP + K_ * TS_;        // [64][128]       8192 (v -> r -> a)
    float* spart = sv + K_ * TS_;        // [ty8][tl8][128] 8192
    float* sGd   = spart + 8 * G_ * TS_; // [g8][64]        512
    float* sw    = sGd + 8 * 64;         // [64]

    int tid = threadIdx.x;
    int ty  = tid >> 5;                  // 0..7 slot group
    int tx  = tid & 31;                  // 0..31 channel group
    int b   = blockIdx.x >> 3;
    int cg  = blockIdx.x & 7;
    int c0  = cg << 7;

    const ull NEG1 = pk2(-1.f, -1.f);

    // tape tile regs: tp[sp][c]: slot pair (ty*16+2sp, +1), channel tx*4+c
    ull tp[8][4];
    #pragma unroll
    for (int sp = 0; sp < 8; sp++)
        #pragma unroll
        for (int c = 0; c < 4; c++) tp[sp][c] = 0ull;

    for (int q = 0; q < NQ_; q++) {
        int T0 = q * K_;
        __syncthreads();   // protect sP/sv from previous iteration's readers
        // ---- stage P, v, Gd, w ----
        #pragma unroll
        for (int i = 0; i < 8; i++) {
            int idx = tid + 256 * i;
            int t = idx >> 5, seg = idx & 31;
            cpa16(sP + t * TS_ + seg * 4,
                  g_P + ((size_t)(T0 + t) * B_ + b) * TS_ + seg * 4);
        }
        #pragma unroll
        for (int i = 0; i < 8; i++) {
            int idx = tid + 256 * i;
            int t = idx >> 5, seg = idx & 31;
            cpa16(sv + t * TS_ + seg * 4,
                  vals + ((size_t)(T0 + t) * B_ + b) * C_ + c0 + seg * 4);
        }
        if (tid < 128)
            cpa16(sGd + tid * 4, g_Gd + (size_t)(b * NQ_ + q) * 512 + tid * 4);
        if (tid < K_)
            sw[tid] = g_hd[(size_t)(T0 + tid) * B_ + b].w;
        cpa_commit_waitall();
        __syncthreads();

        for (int g = 0; g < G_; g++) {
            int t0 = g * 8;

            // ---- phase1: partial ubase for the 8 t's of this group ----
            #pragma unroll 1
            for (int tl = 0; tl < 8; tl++) {
                const ulonglong2* pr = reinterpret_cast<const ulonglong2*>(
                    sP + (t0 + tl) * TS_) + ty * 4;
                ull a0 = 0ull, a1 = 0ull, a2 = 0ull, a3 = 0ull;
                #pragma unroll
                for (int k = 0; k < 4; k++) {
                    ulonglong2 p = pr[k];
                    a0 = fma2(p.x, tp[2 * k][0], a0);
                    a1 = fma2(p.x, tp[2 * k][1], a1);
                    a2 = fma2(p.x, tp[2 * k][2], a2);
                    a3 = fma2(p.x, tp[2 * k][3], a3);
                    a0 = fma2(p.y, tp[2 * k + 1][0], a0);
                    a1 = fma2(p.y, tp[2 * k + 1][1], a1);
                    a2 = fma2(p.y, tp[2 * k + 1][2], a2);
                    a3 = fma2(p.y, tp[2 * k + 1][3], a3);
                }
                float2 f0 = upk2(a0), f1 = upk2(a1), f2 = upk2(a2), f3 = upk2(a3);
                float4 st = make_float4(f0.x + f0.y, f1.x + f1.y,
                                        f2.x + f2.y, f3.x + f3.y);
                *reinterpret_cast<float4*>(spart + ((ty * 8 + tl) * TS_) + tx * 4) = st;
            }
            __syncthreads();

            // ---- reduce partials into sv: r = v - ubase ----
            #pragma unroll
            for (int rr = 0; rr < 2; rr++) {
                int cc = tid + rr * 256;         // ull cell in [0, 512)
                int tl = cc >> 6, cp = cc & 63;
                ull s = *reinterpret_cast<const ull*>(spart + tl * TS_ + cp * 2);
                #pragma unroll
                for (int yy = 1; yy < 8; yy++)
                    s = add2(s, *reinterpret_cast<const ull*>(
                                    spart + (yy * 8 + tl) * TS_ + cp * 2));
                ull* pv = reinterpret_cast<ull*>(sv + (t0 + tl) * TS_ + cp * 2);
                *pv = fma2(s, NEG1, *pv);
            }
            __syncthreads();

            // ---- solve: eager 8x8 triangular, one thread per channel ----
            if (tid < 128) {
                int c = tid;
                const float* Gg = sGd + g * 64;
                float at[8];
                #pragma unroll
                for (int j = 0; j < 8; j++) {
                    float u = 0.f;
                    #pragma unroll
                    for (int jj = 0; jj < 8; jj++)
                        if (jj < j) u += at[jj] * Gg[jj * 8 + j];
                    float a = sw[t0 + j] * (sv[(t0 + j) * TS_ + c] - u);
                    at[j] = a;
                    sv[(t0 + j) * TS_ + c] = a;
                }
            }
            __syncthreads();

            // ---- phase3: tape += p_t (x) a_t for the group ----
            #pragma unroll 1
            for (int tl = 0; tl < 8; tl++) {
                const ulonglong2* pr = reinterpret_cast<const ulonglong2*>(
                    sP + (t0 + tl) * TS_) + ty * 4;
                float4 av = *reinterpret_cast<const float4*>(sv + (t0 + tl) * TS_ + tx * 4);
                ull b0 = pk2(av.x, av.x), b1 = pk2(av.y, av.y);
                ull b2 = pk2(av.z, av.z), b3 = pk2(av.w, av.w);
                #pragma unroll
                for (int k = 0; k < 4; k++) {
                    ulonglong2 p = pr[k];
                    tp[2 * k][0] = fma2(p.x, b0, tp[2 * k][0]);
                    tp[2 * k][1] = fma2(p.x, b1, tp[2 * k][1]);
                    tp[2 * k][2] = fma2(p.x, b2, tp[2 * k][2]);
                    tp[2 * k][3] = fma2(p.x, b3, tp[2 * k][3]);
                    tp[2 * k + 1][0] = fma2(p.y, b0, tp[2 * k + 1][0]);
                    tp[2 * k + 1][1] = fma2(p.y, b1, tp[2 * k + 1][1]);
                    tp[2 * k + 1][2] = fma2(p.y, b2, tp[2 * k + 1][2]);
                    tp[2 * k + 1][3] = fma2(p.y, b3, tp[2 * k + 1][3]);
                }
            }
        }
    }

    // ---- write final tape: coalesced STG.128 ----
    #pragma unroll
    for (int sp = 0; sp < 8; sp++) {
        float2 r0 = upk2(tp[sp][0]), r1 = upk2(tp[sp][1]);
        float2 r2 = upk2(tp[sp][2]), r3 = upk2(tp[sp][3]);
        int l0 = ty * 16 + 2 * sp;
        float4* d0 = reinterpret_cast<float4*>(
            g_tape + ((size_t)l0 * B_ + b) * C_ + c0 + tx * 4);
        float4* d1 = reinterpret_cast<float4*>(
            g_tape + ((size_t)(l0 + 1) * B_ + b) * C_ + c0 + tx * 4);
        *d0 = make_float4(r0.x, r1.x, r2.x, r3.x);
        *d1 = make_float4(r0.y, r1.y, r2.y, r3.y);
    }
}

// ---------------------------------------------------------------------------
// Phase D: LayerNorm + out = h @ Wo^T + bo. Warp-per-row, 4 rows per warp
// to amortize the 40KB Wo staging. grid = TS*B/32.
// ---------------------------------------------------------------------------
__global__ void __launch_bounds__(256) decode_kernel(
    const float* __restrict__ ln_g, const float* __restrict__ ln_b,
    const float* __restrict__ Wo,   const float* __restrict__ bo,
    float* __restrict__ out)
{
    __shared__ float sWo[V_ * C_];   // 40 KB
    int tid = threadIdx.x, lane = tid & 31, wp = tid >> 5;
    for (int i = tid; i < V_ * C_; i += 256) sWo[i] = Wo[i];
    __syncthreads();

    const float4* g4 = reinterpret_cast<const float4*>(ln_g);
    const float4* e4 = reinterpret_cast<const float4*>(ln_b);

    #pragma unroll 1
    for (int r = 0; r < 4; r++) {
        int row = blockIdx.x * 32 + wp * 4 + r;      // row = l*B + b
        const float4* src = reinterpret_cast<const float4*>(g_tape + (size_t)row * C_);
        float4 x[8];
        #pragma unroll
        for (int k = 0; k < 8; k++) x[k] = src[lane + 32 * k];

        float s = 0.f, qq = 0.f;
        #pragma unroll
        for (int k = 0; k < 8; k++) {
            s  += (x[k].x + x[k].y) + (x[k].z + x[k].w);
            qq += (x[k].x*x[k].x + x[k].y*x[k].y) + (x[k].z*x[k].z + x[k].w*x[k].w);
        }
        #pragma unroll
        for (int o = 16; o; o >>= 1) {
            s  += __shfl_xor_sync(0xffffffffu, s, o);
            qq += __shfl_xor_sync(0xffffffffu, qq, o);
        }
        float mu = s * (1.f / C_);
        float rstd = rsqrtf(qq * (1.f / C_) - mu * mu + LN_EPS_);

        #pragma unroll
        for (int k = 0; k < 8; k++) {
            float4 gg = g4[lane + 32 * k];
            float4 ee = e4[lane + 32 * k];
            x[k].x = (x[k].x - mu) * rstd * gg.x + ee.x;
            x[k].y = (x[k].y - mu) * rstd * gg.y + ee.y;
            x[k].z = (x[k].z - mu) * rstd * gg.z + ee.z;
            x[k].w = (x[k].w - mu) * rstd * gg.w + ee.w;
        }

        #pragma unroll
        for (int v = 0; v < V_; v++) {
            const float4* wv = reinterpret_cast<const float4*>(sWo + v * C_);
            float pp = 0.f;
            #pragma unroll
            for (int k = 0; k < 8; k++) {
                float4 w = wv[lane + 32 * k];
                pp += (x[k].x*w.x + x[k].y*w.y) + (x[k].z*w.z + x[k].w*w.w);
            }
            #pragma unroll
            for (int o = 16; o; o >>= 1) pp += __shfl_xor_sync(0xffffffffu, pp, o);
            if (lane == 0) out[(size_t)row * V_ + v] = pp + bo[v];
        }
    }
}

// ---------------------------------------------------------------------------
extern "C" void kernel_launch(void* const* d_in, const int* in_sizes, int n_in,
                              void* d_out, int out_size)
{
    const float* vals = (const float*)d_in[0];
    const float* Wd   = (const float*)d_in[1];
    const float* bd   = (const float*)d_in[2];
    const float* Wr   = (const float*)d_in[3];
    const float* br   = (const float*)d_in[4];
    const float* lng  = (const float*)d_in[5];
    const float* lnb  = (const float*)d_in[6];
    const float* Wo   = (const float*)d_in[7];
    const float* bo   = (const float*)d_in[8];
    float* out = (float*)d_out;

    const int SMEM_SCAN = (K_ * TS_ + K_ * TS_ + 8 * G_ * TS_ + 8 * 64 + K_) * 4;
    cudaFuncSetAttribute(scan_kernel,
                         cudaFuncAttributeMaxDynamicSharedMemorySize, SMEM_SCAN);

    heads_kernel<<<(S_ * B_) / 32, 256>>>(vals, Wd, bd, Wr, br);
    pos_kernel<<<B_ / 8, 256>>>();
    gramd_kernel<<<B_ * NQ_, 256>>>();
    scan_kernel<<<B_ * (C_ / TS_), 256, SMEM_SCAN>>>(vals);
    decode_kernel<<<(TS_ * B_) / 32, 256>>>(lng, lnb, Wo, bo, out);
}

// round 15
// speedup vs baseline: 1.2160x; 1.0381x over previous
#include <cuda_runtime.h>
#include <cstdint>

#define S_  512
#define B_  64
#define C_  1024
#define V_  10
#define TS_ 128
#define K_  64            // chunk length
#define NQ_ (S_ / K_)     // 8 chunks
#define G_  8             // group size within chunk
#define LN_EPS_ 1e-5f

typedef unsigned long long ull;

// Scratch (allocation-free rule: __device__ globals)
__device__ float  g_P[(size_t)S_ * B_ * TS_];      // pos at step t [t][b][l] (16 MB)
__device__ float4 g_hd[(size_t)S_ * B_];           // (d0,d1,d2,w) per (t,b)
__device__ float  g_Gd[(size_t)B_ * NQ_ * 8 * 64]; // diag 8x8 Gram blocks (1 MB)
__device__ float  g_tape[(size_t)TS_ * B_ * C_];   // final tape [l][b][c] (32 MB)

// ---- packed fp32x2 helpers ----
__device__ __forceinline__ ull fma2(ull a, ull b, ull c) {
    ull d;
    asm("fma.rn.f32x2 %0, %1, %2, %3;" : "=l"(d) : "l"(a), "l"(b), "l"(c));
    return d;
}
__device__ __forceinline__ ull pk2(float lo, float hi) {
    ull r;
    asm("mov.b64 %0, {%1, %2};" : "=l"(r) : "f"(lo), "f"(hi));
    return r;
}
__device__ __forceinline__ float2 upk2(ull x) {
    float2 r;
    asm("mov.b64 {%0, %1}, %2;" : "=f"(r.x), "=f"(r.y) : "l"(x));
    return r;
}
__device__ __forceinline__ void cpa16(void* s, const void* g) {
    unsigned sa = (unsigned)__cvta_generic_to_shared(s);
    asm volatile("cp.async.ca.shared.global [%0], [%1], 16;" :: "r"(sa), "l"(g));
}
__device__ __forceinline__ void cpa_commit_waitall() {
    asm volatile("cp.async.commit_group;");
    asm volatile("cp.async.wait_group 0;" ::: "memory");
}

// ---------------------------------------------------------------------------
// Phase A: heads. dir = softmax(v@Wd^T+bd), w = sigmoid(v@Wr[1]+br[1]).
// 32 rows per block (warp loops 4 rows) to amortize the weight staging.
// ---------------------------------------------------------------------------
__global__ void __launch_bounds__(256) heads_kernel(
    const float* __restrict__ vals,
    const float* __restrict__ Wd, const float* __restrict__ bd,
    const float* __restrict__ Wr, const float* __restrict__ br)
{
    __shared__ float sW[4 * C_];
    int tid = threadIdx.x;
    for (int i = tid; i < 3 * C_; i += 256) sW[i] = Wd[i];
    for (int i = tid; i < C_;     i += 256) sW[3 * C_ + i] = Wr[C_ + i];
    __syncthreads();

    int wp = tid >> 5, lane = tid & 31;
    const float4* w4 = reinterpret_cast<const float4*>(sW);

    #pragma unroll 1
    for (int r = 0; r < 4; r++) {
        int row = blockIdx.x * 32 + wp * 4 + r;        // row = t*B + b
        const float4* v4 = reinterpret_cast<const float4*>(vals + (size_t)row * C_);

        float a0 = 0.f, a1 = 0.f, a2 = 0.f, a3 = 0.f;
        for (int i = lane; i < C_ / 4; i += 32) {
            float4 v = v4[i];
            float4 w;
            w = w4[i];       a0 += v.x*w.x + v.y*w.y + v.z*w.z + v.w*w.w;
            w = w4[256 + i]; a1 += v.x*w.x + v.y*w.y + v.z*w.z + v.w*w.w;
            w = w4[512 + i]; a2 += v.x*w.x + v.y*w.y + v.z*w.z + v.w*w.w;
            w = w4[768 + i]; a3 += v.x*w.x + v.y*w.y + v.z*w.z + v.w*w.w;
        }
        #pragma unroll
        for (int o = 16; o; o >>= 1) {
            a0 += __shfl_xor_sync(0xffffffffu, a0, o);
            a1 += __shfl_xor_sync(0xffffffffu, a1, o);
            a2 += __shfl_xor_sync(0xffffffffu, a2, o);
            a3 += __shfl_xor_sync(0xffffffffu, a3, o);
        }
        if (lane == 0) {
            float z0 = a0 + bd[0], z1 = a1 + bd[1], z2 = a2 + bd[2];
            float m  = fmaxf(z0, fmaxf(z1, z2));
            float e0 = expf(z0 - m), e1 = expf(z1 - m), e2 = expf(z2 - m);
            float inv = 1.f / (e0 + e1 + e2);
            float wg  = 1.f / (1.f + expf(-(a3 + br[1])));
            g_hd[row] = make_float4(e0 * inv, e1 * inv, e2 * inv, wg);
        }
    }
}

// ---------------------------------------------------------------------------
// Phase B: pos evolution. One warp per batch, 4 slots/lane, shuffle neighbors.
// Depth-8 prefetch ring on g_hd so the ~250-cyc L2 latency stays covered.
// ---------------------------------------------------------------------------
__global__ void __launch_bounds__(256) pos_kernel()
{
    int wp = threadIdx.x >> 5, lane = threadIdx.x & 31;
    int b = blockIdx.x * 8 + wp;
    float p0 = (lane == 0) ? 1.f : 0.f, p1 = 0.f, p2 = 0.f, p3 = 0.f;

    float4 D[8];
    #pragma unroll
    for (int k = 0; k < 8; k++) D[k] = g_hd[(size_t)k * B_ + b];

    for (int t = 0; t < S_; t += 8) {
        #pragma unroll
        for (int k = 0; k < 8; k++) {
            int tt = t + k;
            float4* dst = reinterpret_cast<float4*>(g_P + ((size_t)tt * B_ + b) * TS_);
            dst[lane] = make_float4(p0, p1, p2, p3);
            float4 Dk = D[k];
            D[k] = g_hd[(size_t)min(tt + 8, S_ - 1) * B_ + b];
            float d0 = Dk.x, d1 = Dk.y, d2 = Dk.z;
            float lw = __shfl_sync(0xffffffffu, p3, (lane + 31) & 31);
            float rw = __shfl_sync(0xffffffffu, p0, (lane + 1)  & 31);
            float n0 = p1 * d0 + p0 * d1 + lw * d2;
            float n1 = p2 * d0 + p1 * d1 + p0 * d2;
            float n2 = p3 * d0 + p2 * d1 + p1 * d2;
            float n3 = rw * d0 + p3 * d1 + p2 * d2;
            p0 = n0; p1 = n1; p2 = n2; p3 = n3;
        }
    }
}

// ---------------------------------------------------------------------------
// Phase B2: diagonal 8x8 Gram blocks: Gd[b][q][g][jj][j] =
//   p_{T0+8g+jj} . p_{T0+8g+j}
// ---------------------------------------------------------------------------
__global__ void __launch_bounds__(256) gramd_kernel()
{
    __shared__ float sPg[K_][132];
    int tid = threadIdx.x;
    int b = blockIdx.x >> 3, q = blockIdx.x & 7;
    int T0 = q * K_;

    for (int idx = tid; idx < K_ * TS_; idx += 256) {
        int t = idx >> 7, l = idx & 127;
        sPg[t][l] = g_P[((size_t)(T0 + t) * B_ + b) * TS_ + l];
    }
    __syncthreads();

    int w = tid >> 5, lane = tid & 31;   // warp w handles group w
    float* out = g_Gd + (size_t)blockIdx.x * 512 + w * 64;
    #pragma unroll
    for (int e = lane; e < 64; e += 32) {
        int jj = e >> 3, j = e & 7;
        const float* ra = sPg[w * 8 + jj];
        const float* rb = sPg[w * 8 + j];
        float d0 = 0.f, d1 = 0.f;
        #pragma unroll 8
        for (int k = 0; k < 32; k++) {
            float4 x = *reinterpret_cast<const float4*>(ra + 4 * k);
            float4 y = *reinterpret_cast<const float4*>(rb + 4 * k);
            d0 += x.x * y.x + x.y * y.y;
            d1 += x.z * y.z + x.w * y.w;
        }
        out[e] = d0 + d1;
    }
}

// ---------------------------------------------------------------------------
// Phase C: chunked tape scan, 2-D register tiling. Phase1/phase3 are the
// verified 484us forms (UNCHANGED). Single change this round: the separate
// reduce pass is deleted — solve threads inline-sum the 8 ty-partials.
// 2 barriers per group instead of 3.
// ---------------------------------------------------------------------------
__global__ void __launch_bounds__(256, 2) scan_kernel(const float* __restrict__ vals)
{
    extern __shared__ float sm[];
    float* sP    = sm;                   // [64][128]       8192 floats
    float* sv    = sP + K_ * TS_;        // [64][128]       8192 (v -> a)
    float* spart = sv + K_ * TS_;        // [ty8][tl8][128] 8192
    float* sGd   = spart + 8 * G_ * TS_; // [g8][64]        512
    float* sw    = sGd + 8 * 64;         // [64]

    int tid = threadIdx.x;
    int ty  = tid >> 5;                  // 0..7 slot group
    int tx  = tid & 31;                  // 0..31 channel group
    int b   = blockIdx.x >> 3;
    int cg  = blockIdx.x & 7;
    int c0  = cg << 7;

    // tape tile regs: tp[sp][c]: slot pair (ty*16+2sp, +1), channel tx*4+c
    ull tp[8][4];
    #pragma unroll
    for (int sp = 0; sp < 8; sp++)
        #pragma unroll
        for (int c = 0; c < 4; c++) tp[sp][c] = 0ull;

    for (int q = 0; q < NQ_; q++) {
        int T0 = q * K_;
        __syncthreads();   // protect sP/sv from previous iteration's readers
        // ---- stage P, v, Gd, w ----
        #pragma unroll
        for (int i = 0; i < 8; i++) {
            int idx = tid + 256 * i;
            int t = idx >> 5, seg = idx & 31;
            cpa16(sP + t * TS_ + seg * 4,
                  g_P + ((size_t)(T0 + t) * B_ + b) * TS_ + seg * 4);
        }
        #pragma unroll
        for (int i = 0; i < 8; i++) {
            int idx = tid + 256 * i;
            int t = idx >> 5, seg = idx & 31;
            cpa16(sv + t * TS_ + seg * 4,
                  vals + ((size_t)(T0 + t) * B_ + b) * C_ + c0 + seg * 4);
        }
        if (tid < 128)
            cpa16(sGd + tid * 4, g_Gd + (size_t)(b * NQ_ + q) * 512 + tid * 4);
        if (tid < K_)
            sw[tid] = g_hd[(size_t)(T0 + tid) * B_ + b].w;
        cpa_commit_waitall();
        __syncthreads();

        for (int g = 0; g < G_; g++) {
            int t0 = g * 8;

            // ---- phase1: partial ubase for the 8 t's of this group ----
            #pragma unroll 1
            for (int tl = 0; tl < 8; tl++) {
                const ulonglong2* pr = reinterpret_cast<const ulonglong2*>(
                    sP + (t0 + tl) * TS_) + ty * 4;
                ull a0 = 0ull, a1 = 0ull, a2 = 0ull, a3 = 0ull;
                #pragma unroll
                for (int k = 0; k < 4; k++) {
                    ulonglong2 p = pr[k];
                    a0 = fma2(p.x, tp[2 * k][0], a0);
                    a1 = fma2(p.x, tp[2 * k][1], a1);
                    a2 = fma2(p.x, tp[2 * k][2], a2);
                    a3 = fma2(p.x, tp[2 * k][3], a3);
                    a0 = fma2(p.y, tp[2 * k + 1][0], a0);
                    a1 = fma2(p.y, tp[2 * k + 1][1], a1);
                    a2 = fma2(p.y, tp[2 * k + 1][2], a2);
                    a3 = fma2(p.y, tp[2 * k + 1][3], a3);
                }
                float2 f0 = upk2(a0), f1 = upk2(a1), f2 = upk2(a2), f3 = upk2(a3);
                float4 st = make_float4(f0.x + f0.y, f1.x + f1.y,
                                        f2.x + f2.y, f3.x + f3.y);
                *reinterpret_cast<float4*>(spart + ((ty * 8 + tl) * TS_) + tx * 4) = st;
            }
            __syncthreads();

            // ---- solve: inline 8-way partial sum + eager 8x8 triangular ----
            if (tid < 128) {
                int c = tid;
                const float* Gg = sGd + g * 64;
                float at[8];
                #pragma unroll
                for (int j = 0; j < 8; j++) {
                    const float* pp = spart + j * TS_ + c;
                    float s01 = pp[0]        + pp[8  * TS_];
                    float s23 = pp[16 * TS_] + pp[24 * TS_];
                    float s45 = pp[32 * TS_] + pp[40 * TS_];
                    float s67 = pp[48 * TS_] + pp[56 * TS_];
                    float u = (s01 + s23) + (s45 + s67);
                    #pragma unroll
                    for (int jj = 0; jj < 8; jj++)
                        if (jj < j) u += at[jj] * Gg[jj * 8 + j];
                    float a = sw[t0 + j] * (sv[(t0 + j) * TS_ + c] - u);
                    at[j] = a;
                    sv[(t0 + j) * TS_ + c] = a;
                }
            }
            __syncthreads();

            // ---- phase3: tape += p_t (x) a_t for the group ----
            #pragma unroll 1
            for (int tl = 0; tl < 8; tl++) {
                const ulonglong2* pr = reinterpret_cast<const ulonglong2*>(
                    sP + (t0 + tl) * TS_) + ty * 4;
                float4 av = *reinterpret_cast<const float4*>(sv + (t0 + tl) * TS_ + tx * 4);
                ull b0 = pk2(av.x, av.x), b1 = pk2(av.y, av.y);
                ull b2 = pk2(av.z, av.z), b3 = pk2(av.w, av.w);
                #pragma unroll
                for (int k = 0; k < 4; k++) {
                    ulonglong2 p = pr[k];
                    tp[2 * k][0] = fma2(p.x, b0, tp[2 * k][0]);
                    tp[2 * k][1] = fma2(p.x, b1, tp[2 * k][1]);
                    tp[2 * k][2] = fma2(p.x, b2, tp[2 * k][2]);
                    tp[2 * k][3] = fma2(p.x, b3, tp[2 * k][3]);
                    tp[2 * k + 1][0] = fma2(p.y, b0, tp[2 * k + 1][0]);
                    tp[2 * k + 1][1] = fma2(p.y, b1, tp[2 * k + 1][1]);
                    tp[2 * k + 1][2] = fma2(p.y, b2, tp[2 * k + 1][2]);
                    tp[2 * k + 1][3] = fma2(p.y, b3, tp[2 * k + 1][3]);
                }
            }
        }
    }

    // ---- write final tape: coalesced STG.128 ----
    #pragma unroll
    for (int sp = 0; sp < 8; sp++) {
        float2 r0 = upk2(tp[sp][0]), r1 = upk2(tp[sp][1]);
        float2 r2 = upk2(tp[sp][2]), r3 = upk2(tp[sp][3]);
        int l0 = ty * 16 + 2 * sp;
        float4* d0 = reinterpret_cast<float4*>(
            g_tape + ((size_t)l0 * B_ + b) * C_ + c0 + tx * 4);
        float4* d1 = reinterpret_cast<float4*>(
            g_tape + ((size_t)(l0 + 1) * B_ + b) * C_ + c0 + tx * 4);
        *d0 = make_float4(r0.x, r1.x, r2.x, r3.x);
        *d1 = make_float4(r0.y, r1.y, r2.y, r3.y);
    }
}

// ---------------------------------------------------------------------------
// Phase D: LayerNorm + out = h @ Wo^T + bo. Warp-per-row, 4 rows per warp
// to amortize the 40KB Wo staging. grid = TS*B/32.
// ---------------------------------------------------------------------------
__global__ void __launch_bounds__(256) decode_kernel(
    const float* __restrict__ ln_g, const float* __restrict__ ln_b,
    const float* __restrict__ Wo,   const float* __restrict__ bo,
    float* __restrict__ out)
{
    __shared__ float sWo[V_ * C_];   // 40 KB
    int tid = threadIdx.x, lane = tid & 31, wp = tid >> 5;
    for (int i = tid; i < V_ * C_; i += 256) sWo[i] = Wo[i];
    __syncthreads();

    const float4* g4 = reinterpret_cast<const float4*>(ln_g);
    const float4* e4 = reinterpret_cast<const float4*>(ln_b);

    #pragma unroll 1
    for (int r = 0; r < 4; r++) {
        int row = blockIdx.x * 32 + wp * 4 + r;      // row = l*B + b
        const float4* src = reinterpret_cast<const float4*>(g_tape + (size_t)row * C_);
        float4 x[8];
        #pragma unroll
        for (int k = 0; k < 8; k++) x[k] = src[lane + 32 * k];

        float s = 0.f, qq = 0.f;
        #pragma unroll
        for (int k = 0; k < 8; k++) {
            s  += (x[k].x + x[k].y) + (x[k].z + x[k].w);
            qq += (x[k].x*x[k].x + x[k].y*x[k].y) + (x[k].z*x[k].z + x[k].w*x[k].w);
        }
        #pragma unroll
        for (int o = 16; o; o >>= 1) {
            s  += __shfl_xor_sync(0xffffffffu, s, o);
            qq += __shfl_xor_sync(0xffffffffu, qq, o);
        }
        float mu = s * (1.f / C_);
        float rstd = rsqrtf(qq * (1.f / C_) - mu * mu + LN_EPS_);

        #pragma unroll
        for (int k = 0; k < 8; k++) {
            float4 gg = g4[lane + 32 * k];
            float4 ee = e4[lane + 32 * k];
            x[k].x = (x[k].x - mu) * rstd * gg.x + ee.x;
            x[k].y = (x[k].y - mu) * rstd * gg.y + ee.y;
            x[k].z = (x[k].z - mu) * rstd * gg.z + ee.z;
            x[k].w = (x[k].w - mu) * rstd * gg.w + ee.w;
        }

        #pragma unroll
        for (int v = 0; v < V_; v++) {
            const float4* wv = reinterpret_cast<const float4*>(sWo + v * C_);
            float pp = 0.f;
            #pragma unroll
            for (int k = 0; k < 8; k++) {
                float4 w = wv[lane + 32 * k];
                pp += (x[k].x*w.x + x[k].y*w.y) + (x[k].z*w.z + x[k].w*w.w);
            }
            #pragma unroll
            for (int o = 16; o; o >>= 1) pp += __shfl_xor_sync(0xffffffffu, pp, o);
            if (lane == 0) out[(size_t)row * V_ + v] = pp + bo[v];
        }
    }
}

// ---------------------------------------------------------------------------
extern "C" void kernel_launch(void* const* d_in, const int* in_sizes, int n_in,
                              void* d_out, int out_size)
{
    const float* vals = (const float*)d_in[0];
    const float* Wd   = (const float*)d_in[1];
    const float* bd   = (const float*)d_in[2];
    const float* Wr   = (const float*)d_in[3];
    const float* br   = (const float*)d_in[4];
    const float* lng  = (const float*)d_in[5];
    const float* lnb  = (const float*)d_in[6];
    const float* Wo   = (const float*)d_in[7];
    const float* bo   = (const float*)d_in[8];
    float* out = (float*)d_out;

    const int SMEM_SCAN = (K_ * TS_ + K_ * TS_ + 8 * G_ * TS_ + 8 * 64 + K_) * 4;
    cudaFuncSetAttribute(scan_kernel,
                         cudaFuncAttributeMaxDynamicSharedMemorySize, SMEM_SCAN);

    heads_kernel<<<(S_ * B_) / 32, 256>>>(vals, Wd, bd, Wr, br);
    pos_kernel<<<B_ / 8, 256>>>();
    gramd_kernel<<<B_ * NQ_, 256>>>();
    scan_kernel<<<B_ * (C_ / TS_), 256, SMEM_SCAN>>>(vals);
    decode_kernel<<<(TS_ * B_) / 32, 256>>>(lng, lnb, Wo, bo, out);
}